// round 3
// baseline (speedup 1.0000x reference)
#include <cuda_runtime.h>
#include <math.h>

// BackflowNet: B=128, N=64, D=2, H=64, M=64, L=2.   (M is 64 — NOT 2!)
// One CTA per batch. he1 (layer-1 edge state, 1MB/batch) in __device__ scratch.
// Hoists: e2v W2 out of the i-sum (linear), v2e hv-projection per source node.

#define TPB 256

__device__ float g_he[128u * 64u * 64u * 64u];   // [b][i][j][m] scratch for he after layer-1

__device__ __forceinline__ float gelu_exact(float x) {
    return 0.5f * x * (1.0f + erff(x * 0.70710678118654752f));
}

// SMEM layout (floats)
#define OFF_HV   0        // [64][64]
#define OFF_ACC  4096     // [64][64]
#define OFF_PRE  8192     // [64][64]
#define OFF_A    12288    // [64][68] padded tile
#define OFF_B    16640    // [64][68]
#define OFF_W0   20992    // 4 weight slots [64][64]
#define OFF_W1   25088
#define OFF_W2   29184
#define OFF_W3   33280
#define OFF_XS   37376    // [64][2]
#define OFF_SP   37504    // [64]
#define OFF_EW1  37568    // [4][64] (also node_w1 [3][64] staging)
#define OFF_B0   37824    // 5 bias slots of 64
#define OFF_B1   37888
#define OFF_B2   37952
#define OFF_B3   38016
#define OFF_B4   38080
#define OFF_F4   38144    // [64][4]
#define OFF_DX   38400    // [64][2]
#define OFF_MN   38528    // [2]
#define SMEM_FLOATS 38544
#define SMEM_BYTES (SMEM_FLOATS * 4)

// out[j][m] = post( inscale * (sum_k in[j*istride+k] * w[k*64+m]) + bias[m] + addrow[m] )
// for 64 rows j, 64 cols m; 256 threads, 4x4 register tile each.
__device__ __forceinline__ void mm64(
    const float* __restrict__ in, int istride,
    const float* __restrict__ w,
    const float* __restrict__ bias,     // nullable
    const float* __restrict__ addrow,   // nullable
    float* __restrict__ out, int ostride,
    int act,            // 0 none, 1 gelu, 2 tanh
    float inscale, bool accum, int tid)
{
    const int mb = (tid & 15) * 4;
    const int jb = (tid >> 4) * 4;
    const float* i0 = in + jb * istride;
    const float* i1 = i0 + istride;
    const float* i2 = i1 + istride;
    const float* i3 = i2 + istride;
    float r[4][4];
    #pragma unroll
    for (int v = 0; v < 4; v++)
        #pragma unroll
        for (int u = 0; u < 4; u++) r[v][u] = 0.f;

    #pragma unroll 4
    for (int k = 0; k < 64; k += 4) {
        float4 a0 = *(const float4*)(i0 + k);
        float4 a1 = *(const float4*)(i1 + k);
        float4 a2 = *(const float4*)(i2 + k);
        float4 a3 = *(const float4*)(i3 + k);
        float4 w0 = *(const float4*)(w + (k + 0) * 64 + mb);
        float4 w1 = *(const float4*)(w + (k + 1) * 64 + mb);
        float4 w2 = *(const float4*)(w + (k + 2) * 64 + mb);
        float4 w3 = *(const float4*)(w + (k + 3) * 64 + mb);
        r[0][0]=fmaf(a0.x,w0.x,r[0][0]); r[0][1]=fmaf(a0.x,w0.y,r[0][1]); r[0][2]=fmaf(a0.x,w0.z,r[0][2]); r[0][3]=fmaf(a0.x,w0.w,r[0][3]);
        r[1][0]=fmaf(a1.x,w0.x,r[1][0]); r[1][1]=fmaf(a1.x,w0.y,r[1][1]); r[1][2]=fmaf(a1.x,w0.z,r[1][2]); r[1][3]=fmaf(a1.x,w0.w,r[1][3]);
        r[2][0]=fmaf(a2.x,w0.x,r[2][0]); r[2][1]=fmaf(a2.x,w0.y,r[2][1]); r[2][2]=fmaf(a2.x,w0.z,r[2][2]); r[2][3]=fmaf(a2.x,w0.w,r[2][3]);
        r[3][0]=fmaf(a3.x,w0.x,r[3][0]); r[3][1]=fmaf(a3.x,w0.y,r[3][1]); r[3][2]=fmaf(a3.x,w0.z,r[3][2]); r[3][3]=fmaf(a3.x,w0.w,r[3][3]);
        r[0][0]=fmaf(a0.y,w1.x,r[0][0]); r[0][1]=fmaf(a0.y,w1.y,r[0][1]); r[0][2]=fmaf(a0.y,w1.z,r[0][2]); r[0][3]=fmaf(a0.y,w1.w,r[0][3]);
        r[1][0]=fmaf(a1.y,w1.x,r[1][0]); r[1][1]=fmaf(a1.y,w1.y,r[1][1]); r[1][2]=fmaf(a1.y,w1.z,r[1][2]); r[1][3]=fmaf(a1.y,w1.w,r[1][3]);
        r[2][0]=fmaf(a2.y,w1.x,r[2][0]); r[2][1]=fmaf(a2.y,w1.y,r[2][1]); r[2][2]=fmaf(a2.y,w1.z,r[2][2]); r[2][3]=fmaf(a2.y,w1.w,r[2][3]);
        r[3][0]=fmaf(a3.y,w1.x,r[3][0]); r[3][1]=fmaf(a3.y,w1.y,r[3][1]); r[3][2]=fmaf(a3.y,w1.z,r[3][2]); r[3][3]=fmaf(a3.y,w1.w,r[3][3]);
        r[0][0]=fmaf(a0.z,w2.x,r[0][0]); r[0][1]=fmaf(a0.z,w2.y,r[0][1]); r[0][2]=fmaf(a0.z,w2.z,r[0][2]); r[0][3]=fmaf(a0.z,w2.w,r[0][3]);
        r[1][0]=fmaf(a1.z,w2.x,r[1][0]); r[1][1]=fmaf(a1.z,w2.y,r[1][1]); r[1][2]=fmaf(a1.z,w2.z,r[1][2]); r[1][3]=fmaf(a1.z,w2.w,r[1][3]);
        r[2][0]=fmaf(a2.z,w2.x,r[2][0]); r[2][1]=fmaf(a2.z,w2.y,r[2][1]); r[2][2]=fmaf(a2.z,w2.z,r[2][2]); r[2][3]=fmaf(a2.z,w2.w,r[2][3]);
        r[3][0]=fmaf(a3.z,w2.x,r[3][0]); r[3][1]=fmaf(a3.z,w2.y,r[3][1]); r[3][2]=fmaf(a3.z,w2.z,r[3][2]); r[3][3]=fmaf(a3.z,w2.w,r[3][3]);
        r[0][0]=fmaf(a0.w,w3.x,r[0][0]); r[0][1]=fmaf(a0.w,w3.y,r[0][1]); r[0][2]=fmaf(a0.w,w3.z,r[0][2]); r[0][3]=fmaf(a0.w,w3.w,r[0][3]);
        r[1][0]=fmaf(a1.w,w3.x,r[1][0]); r[1][1]=fmaf(a1.w,w3.y,r[1][1]); r[1][2]=fmaf(a1.w,w3.z,r[1][2]); r[1][3]=fmaf(a1.w,w3.w,r[1][3]);
        r[2][0]=fmaf(a2.w,w3.x,r[2][0]); r[2][1]=fmaf(a2.w,w3.y,r[2][1]); r[2][2]=fmaf(a2.w,w3.z,r[2][2]); r[2][3]=fmaf(a2.w,w3.w,r[2][3]);
        r[3][0]=fmaf(a3.w,w3.x,r[3][0]); r[3][1]=fmaf(a3.w,w3.y,r[3][1]); r[3][2]=fmaf(a3.w,w3.z,r[3][2]); r[3][3]=fmaf(a3.w,w3.w,r[3][3]);
    }
    #pragma unroll
    for (int u = 0; u < 4; u++) {
        float badd = (bias ? bias[mb + u] : 0.f) + (addrow ? addrow[mb + u] : 0.f);
        #pragma unroll
        for (int v = 0; v < 4; v++) {
            float val = fmaf(r[v][u], inscale, badd);
            if (act == 1) val = gelu_exact(val);
            else if (act == 2) val = tanhf(val);
            float* o = out + (jb + v) * ostride + mb + u;
            if (accum) *o += val; else *o = val;
        }
    }
}

__global__ void __launch_bounds__(TPB, 1)
bf_kernel(const float* __restrict__ x, const float* __restrict__ spin,
          const float* __restrict__ node_w1, const float* __restrict__ node_b1,
          const float* __restrict__ node_w2, const float* __restrict__ node_b2,
          const float* __restrict__ edge_w1, const float* __restrict__ edge_b1,
          const float* __restrict__ edge_w2, const float* __restrict__ edge_b2,
          const float* __restrict__ v2e_w1, const float* __restrict__ v2e_b1,
          const float* __restrict__ v2e_w2, const float* __restrict__ v2e_b2,
          const float* __restrict__ e2v_w1, const float* __restrict__ e2v_b1,
          const float* __restrict__ e2v_w2, const float* __restrict__ e2v_b2,
          const float* __restrict__ head_w1, const float* __restrict__ head_b1,
          const float* __restrict__ head_w2, const float* __restrict__ head_b2,
          const float* __restrict__ scale, float* __restrict__ out)
{
    const int b = blockIdx.x;
    const int tid = threadIdx.x;
    extern __shared__ float sm[];
    float* s_hv  = sm + OFF_HV;
    float* s_acc = sm + OFF_ACC;
    float* s_pre = sm + OFF_PRE;
    float* sA    = sm + OFF_A;
    float* sB    = sm + OFF_B;
    float* sW0   = sm + OFF_W0;
    float* sW1   = sm + OFF_W1;
    float* sW2   = sm + OFF_W2;
    float* sW3   = sm + OFF_W3;
    float* s_xs  = sm + OFF_XS;
    float* s_sp  = sm + OFF_SP;
    float* sEW1  = sm + OFF_EW1;
    float* sb0   = sm + OFF_B0;
    float* sb1   = sm + OFF_B1;
    float* sb2   = sm + OFF_B2;
    float* sb3   = sm + OFF_B3;
    float* sb4   = sm + OFF_B4;
    float* s_f4  = sm + OFF_F4;
    float* s_dx  = sm + OFF_DX;
    float* s_mn  = sm + OFF_MN;

    // ---- stage inputs + node weights ----
    if (tid < 128) s_xs[tid] = x[b * 128 + tid];       // OMEGA=1
    if (tid < 64)  s_sp[tid] = spin[b * 64 + tid];
    for (int t = tid; t < 4096; t += TPB) sW0[t] = node_w2[t];
    if (tid < 192) sEW1[tid] = node_w1[tid];
    if (tid < 64) { sb0[tid] = node_b1[tid]; sb1[tid] = node_b2[tid]; }
    __syncthreads();

    // node MLP hidden -> A (padded)
    for (int t = tid; t < 4096; t += TPB) {
        int i = t >> 6, h = t & 63;
        float v = fmaf(s_xs[i * 2], sEW1[h],
                  fmaf(s_xs[i * 2 + 1], sEW1[64 + h],
                  fmaf(s_sp[i], sEW1[128 + h], sb0[h])));
        sA[i * 68 + h] = gelu_exact(v);
    }
    __syncthreads();
    mm64(sA, 68, sW0, sb1, 0, s_hv, 64, 0, 1.f, false, tid);   // hv
    __syncthreads();

    const float inv = 1.0f / 63.0f;
    for (int l = 0; l < 2; l++) {
        // ---- pre[i][m] = hv[i] @ v2e_w1[l][:64] + v2e_b1[l] ----
        for (int t = tid; t < 4096; t += TPB) { sW0[t] = v2e_w1[l * 8192 + t]; s_acc[t] = 0.f; }
        if (tid < 64) sb0[tid] = v2e_b1[l * 64 + tid];
        __syncthreads();
        mm64(s_hv, 64, sW0, sb0, 0, s_pre, 64, 0, 1.f, false, tid);
        __syncthreads();

        // ---- stage row-loop weights ----
        for (int t = tid; t < 4096; t += TPB) {
            sW1[t] = v2e_w1[l * 8192 + 4096 + t];   // he-half of v2e_w1
            sW2[t] = v2e_w2[l * 4096 + t];
            sW3[t] = e2v_w1[l * 4096 + t];
        }
        if (l == 0) {
            for (int t = tid; t < 4096; t += TPB) sW0[t] = edge_w2[t];
            if (tid < 256) sEW1[tid] = edge_w1[tid];
            if (tid < 64) { sb1[tid] = edge_b1[tid]; sb2[tid] = edge_b2[tid]; }
        }
        if (tid < 64) { sb3[tid] = v2e_b2[l * 64 + tid]; sb4[tid] = e2v_b1[l * 64 + tid]; }
        __syncthreads();

        for (int i = 0; i < 64; i++) {
            if (l == 0) {
                if (tid < 64) {   // edge geometry features for row i
                    int j = tid;
                    float d0 = s_xs[j * 2] - s_xs[i * 2];
                    float d1 = s_xs[j * 2 + 1] - s_xs[i * 2 + 1];
                    float r2 = d0 * d0 + d1 * d1;
                    float rr = sqrtf(r2 + 1e-12f);
                    s_f4[j * 4] = d0; s_f4[j * 4 + 1] = d1;
                    s_f4[j * 4 + 2] = rr; s_f4[j * 4 + 3] = r2;
                }
                __syncthreads();
                for (int t = tid; t < 4096; t += TPB) {   // edge MLP hidden
                    int j = t >> 6, m = t & 63;
                    float v = fmaf(s_f4[j * 4], sEW1[m],
                              fmaf(s_f4[j * 4 + 1], sEW1[64 + m],
                              fmaf(s_f4[j * 4 + 2], sEW1[128 + m],
                              fmaf(s_f4[j * 4 + 3], sEW1[192 + m], sb1[m]))));
                    sA[j * 68 + m] = gelu_exact(v);
                }
                __syncthreads();
                mm64(sA, 68, sW0, sb2, 0, sB, 68, 0, 1.f, false, tid);   // he0
                __syncthreads();
            } else {
                const float* src = g_he + ((size_t)b << 18) + ((size_t)i << 12);
                for (int t = tid; t < 4096; t += TPB) sB[(t >> 6) * 68 + (t & 63)] = src[t];
                __syncthreads();
            }
            // v2e hidden: gelu(pre[i] + he @ W1)
            mm64(sB, 68, sW1, 0, s_pre + i * 64, sA, 68, 1, 1.f, false, tid);
            __syncthreads();
            // new he: hidden @ W2 + b2
            mm64(sA, 68, sW2, sb3, 0, sB, 68, 0, 1.f, false, tid);
            __syncthreads();
            if (l == 0) {
                float* dst = g_he + ((size_t)b << 18) + ((size_t)i << 12);
                for (int t = tid; t < 4096; t += TPB) dst[t] = sB[(t >> 6) * 68 + (t & 63)];
            }
            // g = gelu(he @ e2v_w1 + b1)
            mm64(sB, 68, sW3, sb4, 0, sA, 68, 1, 1.f, false, tid);
            __syncthreads();
            // masked accumulate over source i into acc[j]
            for (int t = tid; t < 4096; t += TPB) {
                int j = t >> 6;
                if (j != i) s_acc[t] += sA[(t >> 6) * 68 + (t & 63)];
            }
            __syncthreads();
        }
        // ---- hv[j] += (acc[j]*inv) @ e2v_w2 + e2v_b2 ----
        for (int t = tid; t < 4096; t += TPB) sW0[t] = e2v_w2[l * 4096 + t];
        if (tid < 64) sb0[tid] = e2v_b2[l * 64 + tid];
        __syncthreads();
        mm64(s_acc, 64, sW0, sb0, 0, s_hv, 64, 0, inv, true, tid);
        __syncthreads();
    }

    // ---- head ----
    for (int t = tid; t < 4096; t += TPB) sW0[t] = head_w1[t];
    if (tid < 64) sb0[tid] = head_b1[tid];
    __syncthreads();
    mm64(s_hv, 64, sW0, sb0, 0, sA, 68, 2, 1.f, false, tid);   // tanh hidden
    __syncthreads();
    if (tid < 128) {
        int j = tid >> 1, d = tid & 1;
        float sp = log1pf(expf(scale[0]));
        float s = head_b2[d];
        const float* a = sA + j * 68;
        #pragma unroll
        for (int k = 0; k < 64; k++) s = fmaf(a[k], head_w2[k * 2 + d], s);
        s_dx[tid] = s * sp;
    }
    __syncthreads();
    if (tid < 2) {
        float s = 0.f;
        #pragma unroll
        for (int j = 0; j < 64; j++) s += s_dx[j * 2 + tid];
        s_mn[tid] = s * (1.0f / 64.0f);
    }
    __syncthreads();
    if (tid < 128) out[b * 128 + tid] = s_dx[tid] - s_mn[tid & 1];
}

extern "C" void kernel_launch(void* const* d_in, const int* in_sizes, int n_in,
                              void* d_out, int out_size) {
    (void)out_size;
    // dict-order sizes: x 16384, spin 8192, node_w1 192, node_b1 64, node_w2 4096,
    // node_b2 64, edge_w1 256, edge_b1 64, edge_w2 4096, edge_b2 64,
    // v2e_w1 16384, v2e_b1 128, v2e_w2 8192, v2e_b2 128, e2v_w1 8192,
    // e2v_b1 128, e2v_w2 8192, e2v_b2 128, head_w1 4096, head_b1 64,
    // head_w2 128, head_b2 2, scale 1
    const float* ptr[23];
    bool dict_order = (n_in >= 23 && in_sizes[0] == 16384 && in_sizes[2] == 192);
    if (dict_order) {
        for (int i = 0; i < 23; i++) ptr[i] = (const float*)d_in[i];
    } else {
        // alphabetical: e2v_b1,e2v_b2,e2v_w1,e2v_w2,edge_b1,edge_b2,edge_w1,edge_w2,
        // head_b1,head_b2,head_w1,head_w2,node_b1,node_b2,node_w1,node_w2,scale,
        // spin,v2e_b1,v2e_b2,v2e_w1,v2e_w2,x
        static const int alpha_to_dict[23] = {
            15, 17, 14, 16,  7,  9,  6,  8, 19, 21, 18, 20,
             3,  5,  2,  4, 22,  1, 11, 13, 10, 12,  0
        };
        for (int i = 0; i < 23; i++) ptr[alpha_to_dict[i]] = (const float*)d_in[i];
    }
    float* out = (float*)d_out;

    cudaFuncSetAttribute(bf_kernel, cudaFuncAttributeMaxDynamicSharedMemorySize, SMEM_BYTES);
    bf_kernel<<<128, TPB, SMEM_BYTES>>>(
        ptr[0], ptr[1], ptr[2], ptr[3], ptr[4], ptr[5],
        ptr[6], ptr[7], ptr[8], ptr[9],
        ptr[10], ptr[11], ptr[12], ptr[13],
        ptr[14], ptr[15], ptr[16], ptr[17],
        ptr[18], ptr[19], ptr[20], ptr[21], ptr[22], out);
}

// round 4
// speedup vs baseline: 1.1489x; 1.1489x over previous
#include <cuda_runtime.h>
#include <math.h>

// BackflowNet: B=128, N=64, D=2, H=64, M=64, L=2.
// One CTA per batch. G=2 dual-row GEMMs reuse weight registers across two
// i-row tiles (1.5x less LDS per FMA, 2x ILP). Masked accumulation fused
// into the e2v GEMM epilogue. Layer-1 reads he directly from global scratch.

#define TPB 256

__device__ float g_he[128u * 64u * 64u * 64u];   // [b][i][j][m]

__device__ __forceinline__ float gelu_exact(float x) {
    return 0.5f * x * (1.0f + erff(x * 0.70710678118654752f));
}

// SMEM layout (floats)
#define OFF_HV   0        // [64][64]
#define OFF_ACC  4096     // [64][64]
#define OFF_PRE  8192     // [64][64]
#define OFF_A0   12288    // [64][68]
#define OFF_A1   16640
#define OFF_B0   20992
#define OFF_B1   25344
#define OFF_W1   29696    // [64][64]
#define OFF_W2   33792
#define OFF_W3   37888
#define OFF_W0   41984    // transient weight slot
#define OFF_XS   46080    // [64][2]
#define OFF_SP   46208    // [64]
#define OFF_EW1  46272    // [4][64]
#define OFF_SB0  46528
#define OFF_SB1  46592
#define OFF_SB2  46656
#define OFF_SB3  46720
#define OFF_SB4  46784
#define OFF_F4   46848    // [2][64][4]
#define OFF_DX   47360    // [64][2]
#define OFF_MN   47488
#define SMEM_FLOATS 47492
#define SMEM_BYTES (SMEM_FLOATS * 4)

#define RANK1(rr, av, wv) \
    rr[0]=fmaf(av, wv.x, rr[0]); rr[1]=fmaf(av, wv.y, rr[1]); \
    rr[2]=fmaf(av, wv.z, rr[2]); rr[3]=fmaf(av, wv.w, rr[3]);
#define TILE4(R, a0v, a1v, a2v, a3v, W) \
    RANK1(R[0], a0v, W) RANK1(R[1], a1v, W) RANK1(R[2], a2v, W) RANK1(R[3], a3v, W)

// ---- single-tile 64x64x64 GEMM (4x4 tiles, 256 threads) ----
__device__ __forceinline__ void mm64(
    const float* __restrict__ in, int istride,
    const float* __restrict__ w,
    const float* __restrict__ bias,
    const float* __restrict__ addrow,
    float* __restrict__ out, int ostride,
    int act, float inscale, bool accum, int tid)
{
    const int mb = (tid & 15) * 4;
    const int jb = (tid >> 4) * 4;
    const float* i0 = in + jb * istride;
    const float* i1 = i0 + istride;
    const float* i2 = i1 + istride;
    const float* i3 = i2 + istride;
    float r[4][4] = {};
    #pragma unroll 4
    for (int k = 0; k < 64; k += 4) {
        float4 w0 = *(const float4*)(w + (k + 0) * 64 + mb);
        float4 w1 = *(const float4*)(w + (k + 1) * 64 + mb);
        float4 w2 = *(const float4*)(w + (k + 2) * 64 + mb);
        float4 w3 = *(const float4*)(w + (k + 3) * 64 + mb);
        float4 a0 = *(const float4*)(i0 + k);
        float4 a1 = *(const float4*)(i1 + k);
        float4 a2 = *(const float4*)(i2 + k);
        float4 a3 = *(const float4*)(i3 + k);
        TILE4(r, a0.x, a1.x, a2.x, a3.x, w0)
        TILE4(r, a0.y, a1.y, a2.y, a3.y, w1)
        TILE4(r, a0.z, a1.z, a2.z, a3.z, w2)
        TILE4(r, a0.w, a1.w, a2.w, a3.w, w3)
    }
    #pragma unroll
    for (int u = 0; u < 4; u++) {
        float badd = (bias ? bias[mb + u] : 0.f) + (addrow ? addrow[mb + u] : 0.f);
        #pragma unroll
        for (int v = 0; v < 4; v++) {
            float val = fmaf(r[v][u], inscale, badd);
            if (act == 1) val = gelu_exact(val);
            else if (act == 2) val = tanhf(val);
            float* o = out + (jb + v) * ostride + mb + u;
            if (accum) *o += val; else *o = val;
        }
    }
}

// ---- dual-tile GEMM: two A tiles share the weight registers ----
__device__ __forceinline__ void mm_dual(
    const float* __restrict__ inA, const float* __restrict__ inB, int istride,
    const float* __restrict__ w,
    const float* __restrict__ bias,
    const float* __restrict__ add0, const float* __restrict__ add1,
    float* __restrict__ out0, float* __restrict__ out1, int ostride,
    float* __restrict__ gm0, float* __restrict__ gm1,   // optional global mirrors [j*64+m]
    float* __restrict__ accp, int i0r, int i1r,          // masked-accumulate mode
    int act, int tid)
{
    const int mb = (tid & 15) * 4;
    const int jb = (tid >> 4) * 4;
    const float* A0 = inA + jb * istride;
    const float* A1 = A0 + istride;
    const float* A2 = A1 + istride;
    const float* A3 = A2 + istride;
    const float* B0 = inB + jb * istride;
    const float* B1 = B0 + istride;
    const float* B2 = B1 + istride;
    const float* B3 = B2 + istride;
    float r0[4][4] = {}, r1[4][4] = {};
    #pragma unroll 4
    for (int k = 0; k < 64; k += 4) {
        float4 w0 = *(const float4*)(w + (k + 0) * 64 + mb);
        float4 w1 = *(const float4*)(w + (k + 1) * 64 + mb);
        float4 w2 = *(const float4*)(w + (k + 2) * 64 + mb);
        float4 w3 = *(const float4*)(w + (k + 3) * 64 + mb);
        float4 a0 = *(const float4*)(A0 + k);
        float4 a1 = *(const float4*)(A1 + k);
        float4 a2 = *(const float4*)(A2 + k);
        float4 a3 = *(const float4*)(A3 + k);
        TILE4(r0, a0.x, a1.x, a2.x, a3.x, w0)
        TILE4(r0, a0.y, a1.y, a2.y, a3.y, w1)
        TILE4(r0, a0.z, a1.z, a2.z, a3.z, w2)
        TILE4(r0, a0.w, a1.w, a2.w, a3.w, w3)
        a0 = *(const float4*)(B0 + k);
        a1 = *(const float4*)(B1 + k);
        a2 = *(const float4*)(B2 + k);
        a3 = *(const float4*)(B3 + k);
        TILE4(r1, a0.x, a1.x, a2.x, a3.x, w0)
        TILE4(r1, a0.y, a1.y, a2.y, a3.y, w1)
        TILE4(r1, a0.z, a1.z, a2.z, a3.z, w2)
        TILE4(r1, a0.w, a1.w, a2.w, a3.w, w3)
    }
    #pragma unroll
    for (int u = 0; u < 4; u++) {
        float bu = bias ? bias[mb + u] : 0.f;
        float e0 = bu + (add0 ? add0[mb + u] : 0.f);
        float e1 = bu + (add1 ? add1[mb + u] : 0.f);
        #pragma unroll
        for (int v = 0; v < 4; v++) {
            float v0 = r0[v][u] + e0;
            float v1 = r1[v][u] + e1;
            if (act) { v0 = gelu_exact(v0); v1 = gelu_exact(v1); }
            int j = jb + v;
            if (accp) {
                float m0 = (j != i0r) ? v0 : 0.f;
                float m1 = (j != i1r) ? v1 : 0.f;
                accp[j * 64 + mb + u] += m0 + m1;
            } else {
                out0[j * ostride + mb + u] = v0;
                out1[j * ostride + mb + u] = v1;
                if (gm0) {
                    gm0[j * 64 + mb + u] = v0;
                    gm1[j * 64 + mb + u] = v1;
                }
            }
        }
    }
}

__global__ void __launch_bounds__(TPB, 1)
bf_kernel(const float* __restrict__ x, const float* __restrict__ spin,
          const float* __restrict__ node_w1, const float* __restrict__ node_b1,
          const float* __restrict__ node_w2, const float* __restrict__ node_b2,
          const float* __restrict__ edge_w1, const float* __restrict__ edge_b1,
          const float* __restrict__ edge_w2, const float* __restrict__ edge_b2,
          const float* __restrict__ v2e_w1, const float* __restrict__ v2e_b1,
          const float* __restrict__ v2e_w2, const float* __restrict__ v2e_b2,
          const float* __restrict__ e2v_w1, const float* __restrict__ e2v_b1,
          const float* __restrict__ e2v_w2, const float* __restrict__ e2v_b2,
          const float* __restrict__ head_w1, const float* __restrict__ head_b1,
          const float* __restrict__ head_w2, const float* __restrict__ head_b2,
          const float* __restrict__ scale, float* __restrict__ out)
{
    const int b = blockIdx.x;
    const int tid = threadIdx.x;
    extern __shared__ float sm[];
    float* s_hv  = sm + OFF_HV;
    float* s_acc = sm + OFF_ACC;
    float* s_pre = sm + OFF_PRE;
    float* sA0   = sm + OFF_A0;
    float* sA1   = sm + OFF_A1;
    float* sB0   = sm + OFF_B0;
    float* sB1   = sm + OFF_B1;
    float* sW1   = sm + OFF_W1;
    float* sW2   = sm + OFF_W2;
    float* sW3   = sm + OFF_W3;
    float* sW0   = sm + OFF_W0;
    float* s_xs  = sm + OFF_XS;
    float* s_sp  = sm + OFF_SP;
    float* sEW1  = sm + OFF_EW1;
    float* sb0   = sm + OFF_SB0;
    float* sb1   = sm + OFF_SB1;
    float* sb2   = sm + OFF_SB2;
    float* sb3   = sm + OFF_SB3;
    float* sb4   = sm + OFF_SB4;
    float* s_f4  = sm + OFF_F4;
    float* s_dx  = sm + OFF_DX;
    float* s_mn  = sm + OFF_MN;

    float* ghe_b = g_he + ((size_t)b << 18);

    // ---- stage inputs + node weights ----
    if (tid < 128) s_xs[tid] = x[b * 128 + tid];
    if (tid < 64)  s_sp[tid] = spin[b * 64 + tid];
    for (int t = tid; t < 4096; t += TPB) sW0[t] = node_w2[t];
    if (tid < 192) sEW1[tid] = node_w1[tid];
    if (tid < 64) { sb0[tid] = node_b1[tid]; sb1[tid] = node_b2[tid]; }
    __syncthreads();

    for (int t = tid; t < 4096; t += TPB) {
        int i = t >> 6, h = t & 63;
        float v = fmaf(s_xs[i * 2], sEW1[h],
                  fmaf(s_xs[i * 2 + 1], sEW1[64 + h],
                  fmaf(s_sp[i], sEW1[128 + h], sb0[h])));
        sA0[i * 68 + h] = gelu_exact(v);
    }
    __syncthreads();
    mm64(sA0, 68, sW0, sb1, 0, s_hv, 64, 0, 1.f, false, tid);
    __syncthreads();

    const float inv = 1.0f / 63.0f;
    for (int l = 0; l < 2; l++) {
        // pre[i][m] = hv[i] @ v2e_w1[l][:64] + v2e_b1[l]
        for (int t = tid; t < 4096; t += TPB) { sW0[t] = v2e_w1[l * 8192 + t]; s_acc[t] = 0.f; }
        if (tid < 64) sb0[tid] = v2e_b1[l * 64 + tid];
        __syncthreads();
        mm64(s_hv, 64, sW0, sb0, 0, s_pre, 64, 0, 1.f, false, tid);
        __syncthreads();

        for (int t = tid; t < 4096; t += TPB) {
            sW1[t] = v2e_w1[l * 8192 + 4096 + t];
            sW2[t] = v2e_w2[l * 4096 + t];
            sW3[t] = e2v_w1[l * 4096 + t];
        }
        if (l == 0) {
            for (int t = tid; t < 4096; t += TPB) sW0[t] = edge_w2[t];
            if (tid < 256) sEW1[tid] = edge_w1[tid];
            if (tid < 64) { sb1[tid] = edge_b1[tid]; sb2[tid] = edge_b2[tid]; }
        }
        if (tid < 64) { sb3[tid] = v2e_b2[l * 64 + tid]; sb4[tid] = e2v_b1[l * 64 + tid]; }
        __syncthreads();

        for (int ip = 0; ip < 32; ip++) {
            const int i0r = 2 * ip, i1r = 2 * ip + 1;
            const float* in0;
            const float* in1;
            int istr;
            if (l == 0) {
                if (tid < 128) {            // geometry features, both rows
                    int g = tid >> 6, j = tid & 63, i = i0r + g;
                    float d0 = s_xs[j * 2] - s_xs[i * 2];
                    float d1 = s_xs[j * 2 + 1] - s_xs[i * 2 + 1];
                    float r2 = d0 * d0 + d1 * d1;
                    float rr = sqrtf(r2 + 1e-12f);
                    float* f = s_f4 + g * 256 + j * 4;
                    f[0] = d0; f[1] = d1; f[2] = rr; f[3] = r2;
                }
                __syncthreads();
                for (int t = tid; t < 8192; t += TPB) {   // edge MLP hidden
                    int g = t >> 12, j = (t >> 6) & 63, m = t & 63;
                    const float* f = s_f4 + g * 256 + j * 4;
                    float v = fmaf(f[0], sEW1[m],
                              fmaf(f[1], sEW1[64 + m],
                              fmaf(f[2], sEW1[128 + m],
                              fmaf(f[3], sEW1[192 + m], sb1[m]))));
                    (g ? sA1 : sA0)[j * 68 + m] = gelu_exact(v);
                }
                __syncthreads();
                mm_dual(sA0, sA1, 68, sW0, sb2, 0, 0, sB0, sB1, 68,
                        0, 0, 0, 0, 0, 0, tid);          // he0 tiles
                __syncthreads();
                in0 = sB0; in1 = sB1; istr = 68;
            } else {
                in0 = ghe_b + ((size_t)i0r << 12);
                in1 = ghe_b + ((size_t)i1r << 12);
                istr = 64;
            }
            // v2e hidden: gelu(pre[i] + he @ W1)
            mm_dual(in0, in1, istr, sW1, 0, s_pre + i0r * 64, s_pre + i1r * 64,
                    sA0, sA1, 68, 0, 0, 0, 0, 0, 1, tid);
            __syncthreads();
            // new he: hidden @ W2 + b2   (mirror to g_he in layer 0)
            mm_dual(sA0, sA1, 68, sW2, sb3, 0, 0, sB0, sB1, 68,
                    (l == 0) ? ghe_b + ((size_t)i0r << 12) : 0,
                    (l == 0) ? ghe_b + ((size_t)i1r << 12) : 0,
                    0, 0, 0, 0, tid);
            __syncthreads();
            // g = gelu(he @ e2v_w1 + b1), fused masked accumulate into acc
            mm_dual(sB0, sB1, 68, sW3, sb4, 0, 0, 0, 0, 0,
                    0, 0, s_acc, i0r, i1r, 1, tid);
            __syncthreads();
        }
        // hv[j] += (acc[j]*inv) @ e2v_w2 + e2v_b2
        for (int t = tid; t < 4096; t += TPB) sW0[t] = e2v_w2[l * 4096 + t];
        if (tid < 64) sb0[tid] = e2v_b2[l * 64 + tid];
        __syncthreads();
        mm64(s_acc, 64, sW0, sb0, 0, s_hv, 64, 0, inv, true, tid);
        __syncthreads();
    }

    // ---- head ----
    for (int t = tid; t < 4096; t += TPB) sW0[t] = head_w1[t];
    if (tid < 64) sb0[tid] = head_b1[tid];
    __syncthreads();
    mm64(s_hv, 64, sW0, sb0, 0, sA0, 68, 2, 1.f, false, tid);
    __syncthreads();
    if (tid < 128) {
        int j = tid >> 1, d = tid & 1;
        float sp = log1pf(expf(scale[0]));
        float s = head_b2[d];
        const float* a = sA0 + j * 68;
        #pragma unroll
        for (int k = 0; k < 64; k++) s = fmaf(a[k], head_w2[k * 2 + d], s);
        s_dx[tid] = s * sp;
    }
    __syncthreads();
    if (tid < 2) {
        float s = 0.f;
        #pragma unroll
        for (int j = 0; j < 64; j++) s += s_dx[j * 2 + tid];
        s_mn[tid] = s * (1.0f / 64.0f);
    }
    __syncthreads();
    if (tid < 128) out[b * 128 + tid] = s_dx[tid] - s_mn[tid & 1];
}

extern "C" void kernel_launch(void* const* d_in, const int* in_sizes, int n_in,
                              void* d_out, int out_size) {
    (void)out_size;
    const float* ptr[23];
    bool dict_order = (n_in >= 23 && in_sizes[0] == 16384 && in_sizes[2] == 192);
    if (dict_order) {
        for (int i = 0; i < 23; i++) ptr[i] = (const float*)d_in[i];
    } else {
        static const int alpha_to_dict[23] = {
            15, 17, 14, 16,  7,  9,  6,  8, 19, 21, 18, 20,
             3,  5,  2,  4, 22,  1, 11, 13, 10, 12,  0
        };
        for (int i = 0; i < 23; i++) ptr[alpha_to_dict[i]] = (const float*)d_in[i];
    }
    float* out = (float*)d_out;

    cudaFuncSetAttribute(bf_kernel, cudaFuncAttributeMaxDynamicSharedMemorySize, SMEM_BYTES);
    bf_kernel<<<128, TPB, SMEM_BYTES>>>(
        ptr[0], ptr[1], ptr[2], ptr[3], ptr[4], ptr[5],
        ptr[6], ptr[7], ptr[8], ptr[9],
        ptr[10], ptr[11], ptr[12], ptr[13],
        ptr[14], ptr[15], ptr[16], ptr[17],
        ptr[18], ptr[19], ptr[20], ptr[21], ptr[22], out);
}

// round 5
// speedup vs baseline: 1.1941x; 1.0394x over previous
#include <cuda_runtime.h>
#include <math.h>

// BackflowNet: B=128, N=64, D=2, H=64, M=64, L=2.
// One CTA per batch. GEMM mainloop in packed f32x2 (FFMA2, 2x fp32 rate).
// G=4 i-rows per pass, 8x8 thread tiles, in-place GEMMs (reg->sync->write).

#define TPB 256

__device__ float g_he[128u * 64u * 64u * 64u];   // [b][i][j][m]

__device__ __forceinline__ float gelu_exact(float x) {
    return 0.5f * x * (1.0f + erff(x * 0.70710678118654752f));
}

__device__ __forceinline__ unsigned long long pk2(float lo, float hi) {
    unsigned long long r;
    asm("mov.b64 %0, {%1, %2};" : "=l"(r) : "f"(lo), "f"(hi));
    return r;
}
__device__ __forceinline__ void upk2(unsigned long long v, float& lo, float& hi) {
    asm("mov.b64 {%0, %1}, %2;" : "=f"(lo), "=f"(hi) : "l"(v));
}
__device__ __forceinline__ void fma2(unsigned long long& d, unsigned long long a, unsigned long long b) {
    asm("fma.rn.f32x2 %0, %1, %2, %0;" : "+l"(d) : "l"(a), "l"(b));
}

// SMEM layout (floats)
#define OFF_HV   0
#define OFF_ACC  4096
#define OFF_PRE  8192
#define OFF_T0   12288        // 4 tiles [64][68]
#define T_STRIDE 4352
#define OFF_W1   29696
#define OFF_W2   33792
#define OFF_W3   37888
#define OFF_W0   41984
#define OFF_XS   46080
#define OFF_SP   46208
#define OFF_EW1  46272        // [4][64]
#define OFF_SB0  46528
#define OFF_SB1  46592
#define OFF_SB2  46656
#define OFF_SB3  46720
#define OFF_SB4  46784
#define OFF_F4   46848        // [4][64][4]
#define OFF_DX   47872
#define OFF_MN   48000
#define SMEM_FLOATS 48004
#define SMEM_BYTES (SMEM_FLOATS * 4)

#define RANK1(rr, av, wv) \
    rr[0]=fmaf(av, wv.x, rr[0]); rr[1]=fmaf(av, wv.y, rr[1]); \
    rr[2]=fmaf(av, wv.z, rr[2]); rr[3]=fmaf(av, wv.w, rr[3]);
#define TILE4(R, a0v, a1v, a2v, a3v, W) \
    RANK1(R[0], a0v, W) RANK1(R[1], a1v, W) RANK1(R[2], a2v, W) RANK1(R[3], a3v, W)

// ---- scalar 64x64x64 GEMM (4x4 tiles, 256 threads) — used for small stages ----
__device__ __forceinline__ void mm64(
    const float* __restrict__ in, int istride,
    const float* __restrict__ w,
    const float* __restrict__ bias,
    const float* __restrict__ addrow,
    float* __restrict__ out, int ostride,
    int act, float inscale, bool accum, int tid)
{
    const int mb = (tid & 15) * 4;
    const int jb = (tid >> 4) * 4;
    const float* i0 = in + jb * istride;
    const float* i1 = i0 + istride;
    const float* i2 = i1 + istride;
    const float* i3 = i2 + istride;
    float r[4][4] = {};
    #pragma unroll 4
    for (int k = 0; k < 64; k += 4) {
        float4 w0 = *(const float4*)(w + (k + 0) * 64 + mb);
        float4 w1 = *(const float4*)(w + (k + 1) * 64 + mb);
        float4 w2 = *(const float4*)(w + (k + 2) * 64 + mb);
        float4 w3 = *(const float4*)(w + (k + 3) * 64 + mb);
        float4 a0 = *(const float4*)(i0 + k);
        float4 a1 = *(const float4*)(i1 + k);
        float4 a2 = *(const float4*)(i2 + k);
        float4 a3 = *(const float4*)(i3 + k);
        TILE4(r, a0.x, a1.x, a2.x, a3.x, w0)
        TILE4(r, a0.y, a1.y, a2.y, a3.y, w1)
        TILE4(r, a0.z, a1.z, a2.z, a3.z, w2)
        TILE4(r, a0.w, a1.w, a2.w, a3.w, w3)
    }
    #pragma unroll
    for (int u = 0; u < 4; u++) {
        float badd = (bias ? bias[mb + u] : 0.f) + (addrow ? addrow[mb + u] : 0.f);
        #pragma unroll
        for (int v = 0; v < 4; v++) {
            float val = fmaf(r[v][u], inscale, badd);
            if (act == 1) val = gelu_exact(val);
            else if (act == 2) val = tanhf(val);
            float* o = out + (jb + v) * ostride + mb + u;
            if (accum) *o += val; else *o = val;
        }
    }
}

// ---- f32x2 GEMM: 64 threads per 64x64 tile (8x8 per thread), in-place safe.
// out = act(in @ w + bias + addrow); row maskrow zeroed after act; optional
// global mirror (stride 64). Contains its own pre-write and post-write syncs.
__device__ __forceinline__ void mmx2(
    const float* __restrict__ in, int istride,
    const float* __restrict__ w,
    const float* __restrict__ bias,
    const float* __restrict__ addrow,
    float* __restrict__ outT,
    float* __restrict__ gmir,
    int maskrow, int act, int t64)
{
    const int mb = (t64 & 7) * 8;
    const int jb = (t64 >> 3) * 8;
    unsigned long long A[8][4];
    #pragma unroll
    for (int r = 0; r < 8; r++)
        #pragma unroll
        for (int p = 0; p < 4; p++) A[r][p] = 0ull;

    const float* base = in + jb * istride;
    #pragma unroll 2
    for (int k = 0; k < 64; k += 4) {
        float4 av[8];
        #pragma unroll
        for (int r = 0; r < 8; r++) av[r] = *(const float4*)(base + r * istride + k);
        #pragma unroll
        for (int kk = 0; kk < 4; kk++) {
            ulonglong2 wlo = *(const ulonglong2*)(w + (k + kk) * 64 + mb);
            ulonglong2 whi = *(const ulonglong2*)(w + (k + kk) * 64 + mb + 4);
            #pragma unroll
            for (int r = 0; r < 8; r++) {
                float a = (kk == 0) ? av[r].x : (kk == 1) ? av[r].y
                        : (kk == 2) ? av[r].z : av[r].w;
                unsigned long long ab = pk2(a, a);
                fma2(A[r][0], ab, wlo.x);
                fma2(A[r][1], ab, wlo.y);
                fma2(A[r][2], ab, whi.x);
                fma2(A[r][3], ab, whi.y);
            }
        }
    }
    // epilogue in registers
    float badd[8];
    #pragma unroll
    for (int u = 0; u < 8; u++)
        badd[u] = (bias ? bias[mb + u] : 0.f) + (addrow ? addrow[mb + u] : 0.f);
    float o[8][8];
    #pragma unroll
    for (int r = 0; r < 8; r++) {
        #pragma unroll
        for (int p = 0; p < 4; p++) {
            float lo, hi;
            upk2(A[r][p], lo, hi);
            float v0 = lo + badd[2 * p];
            float v1 = hi + badd[2 * p + 1];
            if (act) { v0 = gelu_exact(v0); v1 = gelu_exact(v1); }
            o[r][2 * p] = v0; o[r][2 * p + 1] = v1;
        }
        if (jb + r == maskrow) {
            #pragma unroll
            for (int u = 0; u < 8; u++) o[r][u] = 0.f;
        }
    }
    __syncthreads();   // all reads of 'in' complete before in-place writes
    #pragma unroll
    for (int r = 0; r < 8; r++) {
        float4 lo4 = make_float4(o[r][0], o[r][1], o[r][2], o[r][3]);
        float4 hi4 = make_float4(o[r][4], o[r][5], o[r][6], o[r][7]);
        *(float4*)(outT + (jb + r) * 68 + mb)     = lo4;
        *(float4*)(outT + (jb + r) * 68 + mb + 4) = hi4;
        if (gmir) {
            *(float4*)(gmir + (jb + r) * 64 + mb)     = lo4;
            *(float4*)(gmir + (jb + r) * 64 + mb + 4) = hi4;
        }
    }
    __syncthreads();
}

__global__ void __launch_bounds__(TPB, 1)
bf_kernel(const float* __restrict__ x, const float* __restrict__ spin,
          const float* __restrict__ node_w1, const float* __restrict__ node_b1,
          const float* __restrict__ node_w2, const float* __restrict__ node_b2,
          const float* __restrict__ edge_w1, const float* __restrict__ edge_b1,
          const float* __restrict__ edge_w2, const float* __restrict__ edge_b2,
          const float* __restrict__ v2e_w1, const float* __restrict__ v2e_b1,
          const float* __restrict__ v2e_w2, const float* __restrict__ v2e_b2,
          const float* __restrict__ e2v_w1, const float* __restrict__ e2v_b1,
          const float* __restrict__ e2v_w2, const float* __restrict__ e2v_b2,
          const float* __restrict__ head_w1, const float* __restrict__ head_b1,
          const float* __restrict__ head_w2, const float* __restrict__ head_b2,
          const float* __restrict__ scale, float* __restrict__ out)
{
    const int b = blockIdx.x;
    const int tid = threadIdx.x;
    extern __shared__ float sm[];
    float* s_hv  = sm + OFF_HV;
    float* s_acc = sm + OFF_ACC;
    float* s_pre = sm + OFF_PRE;
    float* sW1   = sm + OFF_W1;
    float* sW2   = sm + OFF_W2;
    float* sW3   = sm + OFF_W3;
    float* sW0   = sm + OFF_W0;
    float* s_xs  = sm + OFF_XS;
    float* s_sp  = sm + OFF_SP;
    float* sEW1  = sm + OFF_EW1;
    float* sb0   = sm + OFF_SB0;
    float* sb1   = sm + OFF_SB1;
    float* sb2   = sm + OFF_SB2;
    float* sb3   = sm + OFF_SB3;
    float* sb4   = sm + OFF_SB4;
    float* s_f4  = sm + OFF_F4;
    float* s_dx  = sm + OFF_DX;
    float* s_mn  = sm + OFF_MN;

    float* ghe_b = g_he + ((size_t)b << 18);
    const int g   = tid >> 6;       // tile index 0..3
    const int t64 = tid & 63;
    float* T = sm + OFF_T0 + g * T_STRIDE;

    // ---- stage inputs + node weights ----
    if (tid < 128) s_xs[tid] = x[b * 128 + tid];
    if (tid < 64)  s_sp[tid] = spin[b * 64 + tid];
    for (int t = tid; t < 4096; t += TPB) sW0[t] = node_w2[t];
    if (tid < 192) sEW1[tid] = node_w1[tid];
    if (tid < 64) { sb0[tid] = node_b1[tid]; sb1[tid] = node_b2[tid]; }
    __syncthreads();

    float* T0 = sm + OFF_T0;
    for (int t = tid; t < 4096; t += TPB) {
        int i = t >> 6, h = t & 63;
        float v = fmaf(s_xs[i * 2], sEW1[h],
                  fmaf(s_xs[i * 2 + 1], sEW1[64 + h],
                  fmaf(s_sp[i], sEW1[128 + h], sb0[h])));
        T0[i * 68 + h] = gelu_exact(v);
    }
    __syncthreads();
    mm64(T0, 68, sW0, sb1, 0, s_hv, 64, 0, 1.f, false, tid);
    __syncthreads();

    const float inv = 1.0f / 63.0f;
    for (int l = 0; l < 2; l++) {
        // pre[i][m] = hv[i] @ v2e_w1[l][:64] + v2e_b1[l]
        for (int t = tid; t < 4096; t += TPB) { sW0[t] = v2e_w1[l * 8192 + t]; s_acc[t] = 0.f; }
        if (tid < 64) sb0[tid] = v2e_b1[l * 64 + tid];
        __syncthreads();
        mm64(s_hv, 64, sW0, sb0, 0, s_pre, 64, 0, 1.f, false, tid);
        __syncthreads();

        for (int t = tid; t < 4096; t += TPB) {
            sW1[t] = v2e_w1[l * 8192 + 4096 + t];
            sW2[t] = v2e_w2[l * 4096 + t];
            sW3[t] = e2v_w1[l * 4096 + t];
        }
        if (l == 0) {
            for (int t = tid; t < 4096; t += TPB) sW0[t] = edge_w2[t];
            if (tid < 256) sEW1[tid] = edge_w1[tid];
            if (tid < 64) { sb1[tid] = edge_b1[tid]; sb2[tid] = edge_b2[tid]; }
        }
        if (tid < 64) { sb3[tid] = v2e_b2[l * 64 + tid]; sb4[tid] = e2v_b1[l * 64 + tid]; }
        __syncthreads();

        for (int iq = 0; iq < 16; iq++) {
            const int ig = iq * 4 + g;            // this tile's source row
            float* ghe_row = ghe_b + ((size_t)ig << 12);
            if (l == 0) {
                {   // geometry features: one (g, j) per thread
                    int j = t64;
                    float d0 = s_xs[j * 2] - s_xs[ig * 2];
                    float d1 = s_xs[j * 2 + 1] - s_xs[ig * 2 + 1];
                    float r2 = d0 * d0 + d1 * d1;
                    float rr = sqrtf(r2 + 1e-12f);
                    float* f = s_f4 + g * 256 + j * 4;
                    f[0] = d0; f[1] = d1; f[2] = rr; f[3] = r2;
                }
                __syncthreads();
                for (int t = tid; t < 16384; t += TPB) {     // edge MLP hidden
                    int gg = t >> 12, j = (t >> 6) & 63, m = t & 63;
                    const float* f = s_f4 + gg * 256 + j * 4;
                    float v = fmaf(f[0], sEW1[m],
                              fmaf(f[1], sEW1[64 + m],
                              fmaf(f[2], sEW1[128 + m],
                              fmaf(f[3], sEW1[192 + m], sb1[m]))));
                    (sm + OFF_T0 + gg * T_STRIDE)[j * 68 + m] = gelu_exact(v);
                }
                __syncthreads();
                mmx2(T, 68, sW0, sb2, 0, T, 0, -1, 0, t64);              // he0
                mmx2(T, 68, sW1, 0, s_pre + ig * 64, T, 0, -1, 1, t64);  // v2e hidden
            } else {
                mmx2(ghe_row, 64, sW1, 0, s_pre + ig * 64, T, 0, -1, 1, t64);
            }
            mmx2(T, 68, sW2, sb3, 0, T, (l == 0) ? ghe_row : 0, -1, 0, t64);  // he'
            mmx2(T, 68, sW3, sb4, 0, T, 0, ig, 1, t64);                       // g, masked
            // reduce 4 tiles into acc
            for (int t = tid; t < 1024; t += TPB) {
                int j = t >> 4, q = (t & 15) * 4;
                float4 a  = *(float4*)(s_acc + j * 64 + q);
                float4 v0 = *(const float4*)(sm + OFF_T0 + 0 * T_STRIDE + j * 68 + q);
                float4 v1 = *(const float4*)(sm + OFF_T0 + 1 * T_STRIDE + j * 68 + q);
                float4 v2 = *(const float4*)(sm + OFF_T0 + 2 * T_STRIDE + j * 68 + q);
                float4 v3 = *(const float4*)(sm + OFF_T0 + 3 * T_STRIDE + j * 68 + q);
                a.x += (v0.x + v1.x) + (v2.x + v3.x);
                a.y += (v0.y + v1.y) + (v2.y + v3.y);
                a.z += (v0.z + v1.z) + (v2.z + v3.z);
                a.w += (v0.w + v1.w) + (v2.w + v3.w);
                *(float4*)(s_acc + j * 64 + q) = a;
            }
            __syncthreads();
        }
        // hv[j] += (acc[j]*inv) @ e2v_w2 + e2v_b2
        for (int t = tid; t < 4096; t += TPB) sW0[t] = e2v_w2[l * 4096 + t];
        if (tid < 64) sb0[tid] = e2v_b2[l * 64 + tid];
        __syncthreads();
        mm64(s_acc, 64, sW0, sb0, 0, s_hv, 64, 0, inv, true, tid);
        __syncthreads();
    }

    // ---- head ----
    for (int t = tid; t < 4096; t += TPB) sW0[t] = head_w1[t];
    if (tid < 64) sb0[tid] = head_b1[tid];
    __syncthreads();
    mm64(s_hv, 64, sW0, sb0, 0, T0, 68, 2, 1.f, false, tid);
    __syncthreads();
    if (tid < 128) {
        int j = tid >> 1, d = tid & 1;
        float sp = log1pf(expf(scale[0]));
        float s = head_b2[d];
        const float* a = T0 + j * 68;
        #pragma unroll
        for (int k = 0; k < 64; k++) s = fmaf(a[k], head_w2[k * 2 + d], s);
        s_dx[tid] = s * sp;
    }
    __syncthreads();
    if (tid < 2) {
        float s = 0.f;
        #pragma unroll
        for (int j = 0; j < 64; j++) s += s_dx[j * 2 + tid];
        s_mn[tid] = s * (1.0f / 64.0f);
    }
    __syncthreads();
    if (tid < 128) out[b * 128 + tid] = s_dx[tid] - s_mn[tid & 1];
}

extern "C" void kernel_launch(void* const* d_in, const int* in_sizes, int n_in,
                              void* d_out, int out_size) {
    (void)out_size;
    const float* ptr[23];
    bool dict_order = (n_in >= 23 && in_sizes[0] == 16384 && in_sizes[2] == 192);
    if (dict_order) {
        for (int i = 0; i < 23; i++) ptr[i] = (const float*)d_in[i];
    } else {
        static const int alpha_to_dict[23] = {
            15, 17, 14, 16,  7,  9,  6,  8, 19, 21, 18, 20,
             3,  5,  2,  4, 22,  1, 11, 13, 10, 12,  0
        };
        for (int i = 0; i < 23; i++) ptr[alpha_to_dict[i]] = (const float*)d_in[i];
    }
    float* out = (float*)d_out;

    cudaFuncSetAttribute(bf_kernel, cudaFuncAttributeMaxDynamicSharedMemorySize, SMEM_BYTES);
    bf_kernel<<<128, TPB, SMEM_BYTES>>>(
        ptr[0], ptr[1], ptr[2], ptr[3], ptr[4], ptr[5],
        ptr[6], ptr[7], ptr[8], ptr[9],
        ptr[10], ptr[11], ptr[12], ptr[13],
        ptr[14], ptr[15], ptr[16], ptr[17],
        ptr[18], ptr[19], ptr[20], ptr[21], ptr[22], out);
}